// round 7
// baseline (speedup 1.0000x reference)
#include <cuda_runtime.h>
#include <cstdint>
#include <cfloat>

#define NLEAF   100
#define LSEARCH 10
#define NRE     100
#define MAXB    128
#define MAXN    600000
#define TILE    1024
#define SCORE_CAP (1<<25)
#define MAXTILES  1024
#define SELCAP  4096
#define HBLK    128

/* ------------------------- scratch (__device__ globals) ------------------ */
__device__ int      d_leaf_cnt[NLEAF];
__device__ int      d_leaf_off[NLEAF + 1];
__device__ int      d_leaf_cur[NLEAF];
__device__ int      d_hist_part[HBLK * NLEAF];
__device__ int      d_perm[MAXN];
__device__ unsigned d_qmask[MAXB][4];
__device__ int      d_qleaf[MAXB][LSEARCH];
__device__ int      d_leaf_q[NLEAF][MAXB];
__device__ int      d_leaf_nq[NLEAF];
__device__ int      d_leaf_sbase[NLEAF];
__device__ int      d_tile_leaf[MAXTILES];
__device__ int      d_tile_lo[MAXTILES];
__device__ int      d_ntiles;
__device__ float    d_lut[MAXB * 1024];
__device__ float    d_sbuf[SCORE_CAP];

__device__ __forceinline__ unsigned fkey(float f) {
    unsigned u = __float_as_uint(f);
    return (u & 0x80000000u) ? ~u : (u | 0x80000000u);
}
__device__ __forceinline__ int clampi(int v, int hi) {   /* [0, hi] */
    return max(0, min(v, hi));
}

/* ---- K1: blocks [0,B): centers + top-10 + qmask + LUT                     */
/*          blocks [B,B+HBLK): per-block partial leaf histograms             */
__global__ void k_front(const float* __restrict__ queries,
                        const float* __restrict__ centers,
                        const float* __restrict__ cb,
                        const int* __restrict__ cl,
                        int B, int N) {
    int tid = threadIdx.x;

    if ((int)blockIdx.x >= B) {               /* ---- histogram role ---- */
        int hb = blockIdx.x - B;
        __shared__ int h[NLEAF];
        if (tid < NLEAF) h[tid] = 0;
        __syncthreads();
        int chunk = (N + HBLK - 1) / HBLK;
        int n0 = hb * chunk, n1 = min(n0 + chunk, N);
        for (int n = n0 + tid; n < n1; n += 128)
            atomicAdd(&h[clampi(cl[n], NLEAF - 1)], 1);
        __syncthreads();
        if (tid < NLEAF) d_hist_part[hb * NLEAF + tid] = h[tid];
        return;
    }

    /* ---- centers role ---- */
    int q = blockIdx.x;
    __shared__ float qs[128];
    __shared__ float sc[128];
    __shared__ unsigned smask[4];
    if (tid < 4) smask[tid] = 0u;

    qs[tid] = queries[q * 128 + tid];
    __syncthreads();
    float acc = -FLT_MAX;
    if (tid < NLEAF) {
        acc = 0.f;
        #pragma unroll 8
        for (int d = 0; d < 128; d++) acc += qs[d] * centers[tid * 128 + d];
    }
    sc[tid] = acc;
    __syncthreads();
    if (tid < 32) {
        for (int it = 0; it < LSEARCH; it++) {
            float bv = -FLT_MAX; int bi = 0;
            for (int t = tid; t < NLEAF; t += 32) {
                float v = sc[t];
                if (v > bv || bv == -FLT_MAX) { bv = v; bi = t; }
            }
            #pragma unroll
            for (int o = 16; o; o >>= 1) {
                float ov = __shfl_xor_sync(0xffffffffu, bv, o);
                int   oi = __shfl_xor_sync(0xffffffffu, bi, o);
                if (ov > bv || (ov == bv && oi < bi)) { bv = ov; bi = oi; }
            }
            if (tid == 0) { d_qleaf[q][it] = bi; sc[bi] = -FLT_MAX; }
            __syncwarp();
        }
    }
    __syncthreads();
    if (tid < LSEARCH) {
        int l = clampi(d_qleaf[q][tid], NLEAF - 1);
        atomicOr(&smask[l >> 5], 1u << (l & 31));
    }
    __syncthreads();
    if (tid < 4) d_qmask[q][tid] = smask[tid];

    /* PQ LUT: d_lut[q*1024 + jj*32 + lane] = LUT[2jj+(lane>=16)][lane&15] */
    #pragma unroll
    for (int r = 0; r < 8; r++) {
        int e = tid + 128 * r;
        int lane = e & 31;
        int j = 2 * (e >> 5) + (lane >= 16 ? 1 : 0);
        int c = lane & 15;
        d_lut[q * 1024 + e] = qs[2 * j]     * cb[(j * 16 + c) * 2 + 0]
                            + qs[2 * j + 1] * cb[(j * 16 + c) * 2 + 1];
    }
}

/* ---- K2: reduce hist + leaf query lists + scans + tile table ------------- */
__global__ void k_leafmeta(int B) {
    __shared__ int a[128];
    int tid = threadIdx.x;

    /* reduce partial histograms */
    int cnt = 0;
    if (tid < NLEAF) {
        for (int b = 0; b < HBLK; b++) cnt += d_hist_part[b * NLEAF + tid];
        d_leaf_cnt[tid] = cnt;
        d_leaf_cur[tid] = 0;
    }

    /* per-leaf query lists */
    int nq = 0;
    if (tid < NLEAF) {
        int w = tid >> 5, bit = tid & 31;
        for (int q = 0; q < B; q++) {
            if ((d_qmask[q][w] >> bit) & 1u) {
                d_leaf_q[tid][min(nq, MAXB - 1)] = q;
                nq++;
            }
        }
        nq = min(nq, MAXB);
        d_leaf_nq[tid] = nq;
    }
    __syncthreads();

    /* scan 1: leaf offsets */
    a[tid] = (tid < NLEAF) ? cnt : 0; __syncthreads();
    for (int o = 1; o < 128; o <<= 1) {
        int add = (tid >= o) ? a[tid - o] : 0;
        __syncthreads(); a[tid] += add; __syncthreads();
    }
    if (tid < NLEAF) d_leaf_off[tid] = clampi(a[tid] - cnt, MAXN);
    if (tid == NLEAF - 1) d_leaf_off[NLEAF] = clampi(a[tid], MAXN);
    __syncthreads();

    /* scan 2: score-buffer bases (clamped) */
    long long w = (long long)nq * cnt;
    a[tid] = (tid < NLEAF) ? (int)min(w, (long long)SCORE_CAP) : 0; __syncthreads();
    for (int o = 1; o < 128; o <<= 1) {
        int add = (tid >= o) ? a[tid - o] : 0;
        __syncthreads();
        a[tid] = (int)min((long long)a[tid] + add, (long long)SCORE_CAP);
        __syncthreads();
    }
    if (tid < NLEAF) d_leaf_sbase[tid] = clampi(a[tid] - (int)min(w, (long long)SCORE_CAP), SCORE_CAP);
    __syncthreads();

    /* scan 3: tile table */
    int nt = (tid < NLEAF && nq > 0) ? (cnt + TILE - 1) / TILE : 0;
    a[tid] = nt; __syncthreads();
    for (int o = 1; o < 128; o <<= 1) {
        int add = (tid >= o) ? a[tid - o] : 0;
        __syncthreads(); a[tid] += add; __syncthreads();
    }
    int tb = a[tid] - nt;
    if (tid < NLEAF)
        for (int t = 0; t < nt && tb + t < MAXTILES; t++) {
            d_tile_leaf[tb + t] = tid; d_tile_lo[tb + t] = t * TILE;
        }
    if (tid == 127) d_ntiles = min(a[127], MAXTILES);
}

/* ---- K3: scatter (block-aggregated offsets) ------------------------------ */
#define SCHUNK 2048
__global__ void __launch_bounds__(256) k_scatter(const int* __restrict__ cl, int N) {
    __shared__ int lh[NLEAF], lbase[NLEAF], lcur[NLEAF];
    int tid = threadIdx.x;
    int n0 = blockIdx.x * SCHUNK;
    if (tid < NLEAF) { lh[tid] = 0; lcur[tid] = 0; lbase[tid] = 0; }
    __syncthreads();
    int lv[8];
    #pragma unroll
    for (int r = 0; r < 8; r++) {
        int n = n0 + r * 256 + tid;
        lv[r] = (n < N) ? clampi(cl[n], NLEAF - 1) : -1;
        if (lv[r] >= 0) atomicAdd(&lh[lv[r]], 1);
    }
    __syncthreads();
    if (tid < NLEAF && lh[tid]) lbase[tid] = atomicAdd(&d_leaf_cur[tid], lh[tid]);
    __syncthreads();
    #pragma unroll
    for (int r = 0; r < 8; r++) {
        if (lv[r] >= 0) {
            int p = atomicAdd(&lcur[lv[r]], 1);
            int idx = clampi(d_leaf_off[lv[r]] + lbase[lv[r]] + p, MAXN - 1);
            d_perm[idx] = n0 + r * 256 + tid;
        }
    }
}

/* ---- K4: PQ scoring (warp-shuffle LUT), 512 threads ---------------------- */
__global__ void __launch_bounds__(512) k_score(const int* __restrict__ codes) {
    int bx = blockIdx.x;
    if (bx >= d_ntiles) return;
    int leaf = d_tile_leaf[bx];
    int lo   = d_tile_lo[bx];
    int cnt  = d_leaf_cnt[leaf];
    int count = min(TILE, cnt - lo);
    if (count <= 0) return;
    int off  = d_leaf_off[leaf];

    __shared__ unsigned sh[TILE * 9];
    int tid = threadIdx.x;
    for (int i = tid; i < count; i += 512) {
        int n = d_perm[clampi(off + lo + i, MAXN - 1)];
        const uint4* cp = (const uint4*)(codes + (size_t)n * 64);
        #pragma unroll
        for (int w = 0; w < 8; w++) {
            uint4 a = cp[2 * w], b = cp[2 * w + 1];
            unsigned word = (a.x & 15)        | ((a.y & 15) << 4)
                          | ((a.z & 15) << 8) | ((a.w & 15) << 12)
                          | ((b.x & 15) << 16)| ((b.y & 15) << 20)
                          | ((b.z & 15) << 24)| ((b.w & 15) << 28);
            sh[i * 9 + w] = word;
        }
    }
    __syncthreads();

    int warp = tid >> 5, lane = tid & 31;
    int nq = d_leaf_nq[leaf];
    int sbase = d_leaf_sbase[leaf];

    for (int qi = warp; qi < nq; qi += 16) {
        int q = d_leaf_q[leaf][qi];
        float lut[32];
        const float* lp = d_lut + q * 1024 + lane;
        #pragma unroll
        for (int jj = 0; jj < 32; jj++) lut[jj] = lp[jj * 32];

        int wbase = sbase + qi * cnt + lo;
        for (int c0 = 0; c0 < count; c0 += 32) {
            int c  = c0 + lane;
            int cc = min(c, count - 1);
            unsigned cw[8];
            #pragma unroll
            for (int w = 0; w < 8; w++) cw[w] = sh[cc * 9 + w];
            float a0 = 0.f, a1 = 0.f;
            #pragma unroll
            for (int w = 0; w < 8; w++) {
                #pragma unroll
                for (int t = 0; t < 4; t++) {
                    int n0 = (cw[w] >> (8 * t)) & 15;
                    int n1 = (cw[w] >> (8 * t + 4)) & 15;
                    a0 += __shfl_sync(0xffffffffu, lut[4 * w + t], n0);
                    a1 += __shfl_sync(0xffffffffu, lut[4 * w + t], n1 + 16);
                }
            }
            if (c < count) {
                int idx = wbase + c;
                if (idx >= 0 && idx < SCORE_CAP) d_sbuf[idx] = a0 + a1;
            }
        }
    }
}

/* ---- K5: select top-100 + exact rerank + final top-k --------------------- */
__global__ void __launch_bounds__(512) k_selrank(const float* __restrict__ queries,
                                                 const float* __restrict__ cands,
                                                 const int*   __restrict__ identifiers,
                                                 float* __restrict__ out,
                                                 int B, int N, int kk) {
    int q = blockIdx.x;
    if (q >= B) return;
    int tid = threadIdx.x;
    int warp = tid >> 5, lane = tid & 31;

    __shared__ unsigned long long keys[SELCAP];
    int* hist = (int*)keys;
    __shared__ int csum[512];
    __shared__ int seg_base[LSEARCH], seg_len[LSEARCH], seg_poff[LSEARCH];
    __shared__ int s_bin, s_cnt, s_tot;
    __shared__ float qs[128];
    __shared__ float ex[NRE];
    __shared__ int   sel[NRE];

    if (tid < 128) qs[tid] = queries[q * 128 + tid];
    if (tid < LSEARCH) {
        int l = clampi(d_qleaf[q][tid], NLEAF - 1);
        int nq = d_leaf_nq[l];
        int slot = 0;
        for (int i = 0; i < nq; i++) if (d_leaf_q[l][i] == q) { slot = i; break; }
        seg_base[tid] = clampi(d_leaf_sbase[l] + slot * d_leaf_cnt[l], SCORE_CAP - 1);
        seg_len[tid]  = min(d_leaf_cnt[l], SCORE_CAP - seg_base[tid]);
        seg_poff[tid] = clampi(d_leaf_off[l], MAXN - 1);
    }
    __syncthreads();
    if (tid == 0) {
        int t = 0;
        for (int s = 0; s < LSEARCH; s++) t += seg_len[s];
        s_tot = t;
    }
    __syncthreads();
    int tot = s_tot;

    unsigned T = 0u;
    int attempt = 0;
    int m = 0;

    for (;;) {
        if (tot > SELCAP) {
            for (int i = tid; i < 4096; i += 512) hist[i] = 0;
            if (tid == 0) s_bin = 0;
            __syncthreads();
            int stride = (attempt == 0) ? 16 : 1;
            for (int s = 0; s < LSEARCH; s++) {
                int len = seg_len[s], base = seg_base[s];
                int nel = (len + stride - 1) / stride;
                for (int i = tid; i < nel; i += 512) {
                    unsigned mm = fkey(d_sbuf[base + i * stride]);
                    atomicAdd(&hist[mm >> 20], 1);
                }
            }
            __syncthreads();
            {
                int ssum = 0;
                #pragma unroll
                for (int b = 0; b < 8; b++) ssum += hist[tid * 8 + b];
                csum[tid] = ssum;
            }
            __syncthreads();
            for (int offst = 1; offst < 512; offst <<= 1) {
                int add = (tid + offst < 512) ? csum[tid + offst] : 0;
                __syncthreads();
                csum[tid] += add;
                __syncthreads();
            }
            {
                int running = (tid == 511) ? 0 : csum[tid + 1];
                for (int b = tid * 8 + 7; b >= tid * 8; b--) {
                    int h = hist[b];
                    if (running < NRE && running + h >= NRE) s_bin = b;
                    running += h;
                }
            }
            __syncthreads();
            T = (unsigned)s_bin << 20;
        } else {
            T = 0u;
        }

        /* pipelined compaction with warp-aggregated counter */
        if (tid == 0) s_cnt = 0;
        __syncthreads();
        for (int s = 0; s < LSEARCH; s++) {
            int len = seg_len[s], base = seg_base[s], poff = seg_poff[s];
            int nit = (len + 511) / 512;
            float vcur = (tid < len) ? d_sbuf[base + tid] : -3e38f;
            for (int it = 0; it < nit; it++) {
                int inext = (it + 1) * 512 + tid;
                float vnext = (inext < len) ? d_sbuf[base + inext] : -3e38f;
                int i = it * 512 + tid;
                unsigned mm = fkey(vcur);
                bool pred = (i < len) && (mm >= T);
                unsigned bal = __ballot_sync(0xffffffffu, pred);
                if (bal) {
                    int basep = 0;
                    if (lane == 0) basep = atomicAdd(&s_cnt, __popc(bal));
                    basep = __shfl_sync(0xffffffffu, basep, 0);
                    if (pred) {
                        int pos = basep + __popc(bal & ((1u << lane) - 1u));
                        if (pos < SELCAP) {
                            int id = d_perm[clampi(poff + i, MAXN - 1)];
                            keys[pos] = ((unsigned long long)mm << 32)
                                      | (unsigned)(~(unsigned)id);
                        }
                    }
                }
                vcur = vnext;
            }
        }
        __syncthreads();
        m = s_cnt;
        if (m <= SELCAP || attempt >= 1 || tot <= SELCAP) break;
        attempt = 1;
        __syncthreads();
    }

    int m_eff = min(m, SELCAP);
    int NS = 128;
    while (NS < m_eff) NS <<= 1;
    for (int i = tid; i < NS; i += 512)
        if (i >= m_eff) keys[i] = 0ull;
    __syncthreads();

    /* bitonic sort descending by (score, then id asc via ~id) */
    for (int k2 = 2; k2 <= NS; k2 <<= 1) {
        for (int j = k2 >> 1; j > 0; j >>= 1) {
            for (int idx = tid; idx < (NS >> 1); idx += 512) {
                int i = ((idx / j) * (j << 1)) + (idx % j);
                int p = i + j;
                bool dsc = ((i & k2) == 0);
                unsigned long long a = keys[i], b = keys[p];
                if ((a < b) == dsc) { keys[i] = b; keys[p] = a; }
            }
            __syncthreads();
        }
    }

    if (tid < NRE) {
        unsigned long long kq = (tid < m_eff) ? keys[tid] : 0ull;
        sel[tid] = (kq == 0ull) ? -1 : (int)(~(unsigned)(kq & 0xffffffffull));
    }
    __syncthreads();

    /* exact rerank: 16 warps */
    for (int r = warp; r < NRE; r += 16) {
        int id = sel[r];
        float acc = 0.f;
        bool ok = ((unsigned)id < (unsigned)N);
        if (ok) {
            const float* c = cands + (size_t)id * 128;
            acc = qs[lane] * c[lane] + qs[lane + 32] * c[lane + 32]
                + qs[lane + 64] * c[lane + 64] + qs[lane + 96] * c[lane + 96];
        }
        #pragma unroll
        for (int o = 16; o; o >>= 1) acc += __shfl_xor_sync(0xffffffffu, acc, o);
        if (lane == 0) ex[r] = ok ? acc : -1e30f;
    }
    __syncthreads();

    if (warp == 0) {
        for (int it = 0; it < kk; it++) {
            float bv = -FLT_MAX; int bi = NRE;
            for (int r = lane; r < NRE; r += 32) {
                float v = ex[r];
                if (v > bv || (v == bv && r < bi)) { bv = v; bi = r; }
            }
            #pragma unroll
            for (int o = 16; o; o >>= 1) {
                float ov = __shfl_xor_sync(0xffffffffu, bv, o);
                int   oi = __shfl_xor_sync(0xffffffffu, bi, o);
                if (ov > bv || (ov == bv && oi < bi)) { bv = ov; bi = oi; }
            }
            if (lane == 0) {
                int cid = (bi < NRE) ? sel[bi] : -1;
                out[q * kk + it] = bv;
                float idv = 0.f;
                if ((unsigned)cid < (unsigned)N) idv = (float)identifiers[cid];
                out[(size_t)B * kk + q * kk + it] = idv;
                if (bi < NRE) ex[bi] = -FLT_MAX;
            }
            __syncwarp();
        }
    }
}

/* ---- host launcher ------------------------------------------------------- */
extern "C" void kernel_launch(void* const* d_in, const int* in_sizes, int n_in,
                              void* d_out, int out_size) {
    const float* queries    = (const float*)d_in[0];
    const float* candidates = (const float*)d_in[1];
    const float* centers    = (const float*)d_in[2];
    const float* codebooks  = (const float*)d_in[3];
    const int*   codes      = (const int*)d_in[4];
    const int*   cand_leaf  = (const int*)d_in[5];
    const int*   identifiers= (const int*)d_in[6];

    int B = in_sizes[0] / 128;
    int N = in_sizes[1] / 128;
    if (B < 1) B = 1;
    if (B > MAXB) B = MAXB;
    if (N < 1) N = 1;
    if (N > MAXN) N = MAXN;
    int kk = (B > 0) ? out_size / (2 * B) : 10;
    if (kk <= 0 || kk > NRE) kk = 10;

    float* out = (float*)d_out;

    k_front<<<B + HBLK, 128>>>(queries, centers, codebooks, cand_leaf, B, N); /* 1 */
    k_leafmeta<<<1, 128>>>(B);                                                /* 2 */
    k_scatter<<<(N + SCHUNK - 1) / SCHUNK, 256>>>(cand_leaf, N);              /* 3 */

    int maxTiles = (N + TILE - 1) / TILE + NLEAF;
    if (maxTiles > MAXTILES) maxTiles = MAXTILES;
    k_score<<<maxTiles, 512>>>(codes);                                        /* 4 <- profiled */

    k_selrank<<<B, 512>>>(queries, candidates, identifiers, out, B, N, kk);   /* 5 */
}